// round 1
// baseline (speedup 1.0000x reference)
#include <cuda_runtime.h>

// Problem constants
#define B_TOT    16384
#define F_DENSE  13
#define F_SPARSE 26
#define NF       39          // F_DENSE + F_SPARSE
#define E_DIM    16
#define VOC      100000
#define H1       512
#define H2       256
#define D_IN     624         // (13+26)*16

// Scratch (device globals; no allocation allowed)
__device__ float g_w2eff[H1];
__device__ float g_w1eff[D_IN];
__device__ float g_CONST;

// ---------------------------------------------------------------------------
// Prep 1: w2eff[k] = sum_j Lw2[k,j] * g2[j]    (one warp per k, coalesced)
// ---------------------------------------------------------------------------
__global__ void prep_w2eff(const float* __restrict__ Lw2,
                           const float* __restrict__ g2) {
    int w    = (blockIdx.x * blockDim.x + threadIdx.x) >> 5;   // 0..511
    int lane = threadIdx.x & 31;
    if (w >= H1) return;
    float acc = 0.f;
#pragma unroll
    for (int i = 0; i < H2 / 32; i++) {
        int j = lane + i * 32;
        acc = fmaf(__ldg(Lw2 + w * H2 + j), __ldg(g2 + j), acc);
    }
#pragma unroll
    for (int o = 16; o; o >>= 1) acc += __shfl_xor_sync(0xffffffffu, acc, o);
    if (lane == 0) g_w2eff[w] = acc;
}

// ---------------------------------------------------------------------------
// Prep 2: scalar constant
// CONST = inv^2 * sum_k g1[k]*w2eff[k]*Lb1[k] + inv * sum_k be1[k]*w2eff[k]
//       + inv   * sum_j g2[j]*Lb2[j]          +       sum_j be2[j]
// ---------------------------------------------------------------------------
__global__ void prep_const(const float* __restrict__ Lb1,
                           const float* __restrict__ g1,
                           const float* __restrict__ be1,
                           const float* __restrict__ Lb2,
                           const float* __restrict__ g2,
                           const float* __restrict__ be2) {
    const float inv = rsqrtf(1.f + 1e-5f);
    int k = threadIdx.x;                      // 0..511, one block of 512
    float w2e = g_w2eff[k];
    float v = inv * inv * g1[k] * w2e * Lb1[k] + inv * be1[k] * w2e;
    if (k < H2) v += inv * g2[k] * Lb2[k] + be2[k];
    __shared__ float sh[H1];
    sh[k] = v;
    __syncthreads();
    for (int s = H1 / 2; s; s >>= 1) {
        if (k < s) sh[k] += sh[k + s];
        __syncthreads();
    }
    if (k == 0) g_CONST = sh[0];
}

// ---------------------------------------------------------------------------
// Prep 3: w1eff[d] = sum_k Lw1[d,k] * g1[k] * w2eff[k]   (one warp per d)
// ---------------------------------------------------------------------------
__global__ void prep_w1eff(const float* __restrict__ Lw1,
                           const float* __restrict__ g1) {
    int w    = (blockIdx.x * blockDim.x + threadIdx.x) >> 5;   // 0..623
    int lane = threadIdx.x & 31;
    if (w >= D_IN) return;
    float acc = 0.f;
#pragma unroll
    for (int i = 0; i < H1 / 32; i++) {
        int k = lane + i * 32;
        acc = fmaf(__ldg(Lw1 + w * H1 + k), __ldg(g1 + k) * g_w2eff[k], acc);
    }
#pragma unroll
    for (int o = 16; o; o >>= 1) acc += __shfl_xor_sync(0xffffffffu, acc, o);
    if (lane == 0) g_w1eff[w] = acc;
}

// ---------------------------------------------------------------------------
// Main kernel: 16 lanes per sample (lane = e), 2 samples per warp,
// 256 threads => 16 samples per block.
// ---------------------------------------------------------------------------
__global__ __launch_bounds__(256) void deepfm_main(
    const int*   __restrict__ Xi,
    const float* __restrict__ Xv,
    const float* __restrict__ W1,
    const float* __restrict__ b1,
    const float* __restrict__ emb1,
    const float* __restrict__ W2,
    const float* __restrict__ b2,
    const float* __restrict__ emb2,
    const float* __restrict__ bias,
    float*       __restrict__ out,
    int n) {
    const float inv2 = 1.f / (1.f + 1e-5f);   // inv^2 = 1/(1+eps)

    int tid  = threadIdx.x;
    int lane = tid & 31;
    int e    = lane & 15;          // embedding column handled by this lane
    int sub  = lane >> 4;          // 0/1: which sample within the warp
    int warp = tid >> 5;
    int b    = (blockIdx.x << 4) + (warp << 1) + sub;
    if (b >= n) return;

    const int*   xi = Xi + b * NF;
    const float* xv = Xv + b * NF;

    float fm1 = 0.f;   // first-order sum (partial over this lane's e)
    float se  = 0.f;   // sum_emb[e]
    float ss  = 0.f;   // sumsq[e]
    float hd  = 0.f;   // h . w1eff (partial)

    // Dense features
#pragma unroll
    for (int f = 0; f < F_DENSE; f++) {
        float x  = (float)__ldg(xi + f);
        float v  = __ldg(xv + f);
        int   o  = f * E_DIM + e;
        float sl = fmaf(x, __ldg(W2 + o), __ldg(b2 + o));       // sec_lin
        fm1 = fmaf(fmaf(x, __ldg(W1 + o), __ldg(b1 + o)), v, fm1);
        se += sl;
        ss  = fmaf(sl, sl, ss);
        hd  = fmaf(sl, g_w1eff[o], hd);
    }

    // Sparse features (the memory-bound part: 2 gathers of a 64B row each)
#pragma unroll
    for (int s = 0; s < F_SPARSE; s++) {
        int   idx = __ldg(xi + F_DENSE + s);
        float v   = __ldg(xv + F_DENSE + s);
        int   off = (s * VOC + idx) * E_DIM + e;   // < 41.6M, fits int32
        float a1  = __ldg(emb1 + off);
        float a2  = __ldg(emb2 + off);
        float sev = a2 * v;                        // sec_emb
        fm1 = fmaf(a1, v, fm1);
        se += sev;
        ss  = fmaf(sev, sev, ss);
        hd  = fmaf(sev, g_w1eff[F_DENSE * E_DIM + s * E_DIM + e], hd);
    }

    // Per-lane combined partial; fm_second per-e is exact here
    float r = fm1 + 0.5f * (se * se - ss) + inv2 * hd;

    // Fold 16 lanes (xor<16 stays within each half-warp / sample)
#pragma unroll
    for (int o = 1; o < 16; o <<= 1) r += __shfl_xor_sync(0xffffffffu, r, o);

    if (e == 0) out[b] = r + g_CONST + __ldg(bias + b);
}

// ---------------------------------------------------------------------------
extern "C" void kernel_launch(void* const* d_in, const int* in_sizes, int n_in,
                              void* d_out, int out_size) {
    const int*   Xi   = (const int*)  d_in[0];
    const float* Xv   = (const float*)d_in[1];
    const float* W1   = (const float*)d_in[2];
    const float* b1   = (const float*)d_in[3];
    const float* emb1 = (const float*)d_in[4];
    const float* W2   = (const float*)d_in[5];
    const float* b2   = (const float*)d_in[6];
    const float* emb2 = (const float*)d_in[7];
    const float* Lw1  = (const float*)d_in[8];
    const float* Lb1  = (const float*)d_in[9];
    const float* g1   = (const float*)d_in[10];
    const float* be1  = (const float*)d_in[11];
    const float* Lw2  = (const float*)d_in[12];
    const float* Lb2  = (const float*)d_in[13];
    const float* g2   = (const float*)d_in[14];
    const float* be2  = (const float*)d_in[15];
    const float* bias = (const float*)d_in[16];
    float* out = (float*)d_out;

    // Prep: collapse the MLP to one 624-vector + scalar
    prep_w2eff<<<(H1 * 32 + 255) / 256, 256>>>(Lw2, g2);
    prep_const<<<1, H1>>>(Lb1, g1, be1, Lb2, g2, be2);
    prep_w1eff<<<(D_IN * 32 + 255) / 256, 256>>>(Lw1, g1);

    int n = out_size;
    int blocks = (n + 15) / 16;
    deepfm_main<<<blocks, 256>>>(Xi, Xv, W1, b1, emb1, W2, b2, emb2,
                                 bias, out, n);
}